// round 8
// baseline (speedup 1.0000x reference)
#include <cuda_runtime.h>
#include <math.h>

#define NN 50000
#define EE 400000
#define TT 4
#define F0 128
#define F2 64

// ---------------- device scratch (no allocs allowed) ----------------
__device__ float              g_scores[NN];
__device__ int                g_idx[128];
__device__ float              g_tv[128];
__device__ float              g_inv[2];
__device__ float              g_QA0[128 * 128], g_QB0[128 * 128];
__device__ float              g_QA1[128 * 64],  g_QB1[128 * 64];
__device__ float              g_XW[(size_t)NN * 128];
__device__ float              g_h1[(size_t)NN * 128];
__device__ int                g_rowptr[NN + 1];
__device__ int                g_cursor[NN];      // also used as degree array
__device__ int                g_eid[EE];

// ---------------- helpers ----------------
__device__ __forceinline__ unsigned sortable_u32(float f) {
    unsigned u = __float_as_uint(f);
    return (u & 0x80000000u) ? ~u : (u | 0x80000000u);
}

// packed fp32x2 FMA (sm_100+): d = a*b + d, lanewise IEEE fp32
__device__ __forceinline__ void fma2(unsigned long long& d,
                                     unsigned long long a,
                                     unsigned long long b) {
    asm("fma.rn.f32x2 %0, %1, %2, %0;" : "+l"(d) : "l"(a), "l"(b));
}
__device__ __forceinline__ unsigned long long bcast2(float x) {
    unsigned long long r;
    asm("mov.b64 %0, {%1, %2};" : "=l"(r) : "f"(x), "f"(x));
    return r;
}
__device__ __forceinline__ float2 unpack2(unsigned long long v) {
    float2 r;
    asm("mov.b64 {%0, %1}, %2;" : "=f"(r.x), "=f"(r.y) : "l"(v));
    return r;
}

// ---------------- scorer norms ----------------
__global__ void norm_kernel(const float* __restrict__ s0, const float* __restrict__ s1,
                            float* __restrict__ inv) {
    const float* s = blockIdx.x ? s1 : s0;
    int t = threadIdx.x;           // 128 threads
    float v = s[t]; v *= v;
    __shared__ float red[4];
    for (int o = 16; o; o >>= 1) v += __shfl_xor_sync(0xFFFFFFFFu, v, o);
    if ((t & 31) == 0) red[t >> 5] = v;
    __syncthreads();
    if (t == 0) inv[blockIdx.x] = rsqrtf(red[0] + red[1] + red[2] + red[3]);
}

// ---------------- scores: one warp per node ----------------
__global__ __launch_bounds__(256) void scores_kernel(
    const float* __restrict__ X, const float* __restrict__ scorer,
    const float* __restrict__ mask_t, const float* __restrict__ invp,
    float* __restrict__ out) {
    int warp = (blockIdx.x * blockDim.x + threadIdx.x) >> 5;
    int lane = threadIdx.x & 31;
    if (warp >= NN) return;
    float4 x = reinterpret_cast<const float4*>(X)[(size_t)warp * 32 + lane];
    float4 s = reinterpret_cast<const float4*>(scorer)[lane];
    float d = x.x * s.x + x.y * s.y + x.z * s.z + x.w * s.w;
    for (int o = 16; o; o >>= 1) d += __shfl_xor_sync(0xFFFFFFFFu, d, o);
    if (lane == 0) out[warp] = d * (*invp) + mask_t[warp];
}

// ---------------- fused single-block topk ----------------
__global__ __launch_bounds__(1024) void topk_kernel(
    const float* __restrict__ scores, int k,
    int* __restrict__ idx_out, float* __restrict__ tv_out) {
    __shared__ unsigned h1[1024];
    __shared__ unsigned csum[1024];
    __shared__ unsigned h2[64];
    __shared__ unsigned long long sk[4096];
    __shared__ int s_cb, s_kAbove, s_T16, s_cnt;
    int tid = threadIdx.x;
    h1[tid] = 0;
    if (tid < 64) h2[tid] = 0;
    if (tid == 0) s_cnt = 0;
    __syncthreads();

    // pass 1: coarse histogram over top 10 bits
    const float4* s4 = reinterpret_cast<const float4*>(scores);
    for (int i = tid; i < NN / 4; i += 1024) {
        float4 v = s4[i];
        atomicAdd(&h1[sortable_u32(v.x) >> 22], 1u);
        atomicAdd(&h1[sortable_u32(v.y) >> 22], 1u);
        atomicAdd(&h1[sortable_u32(v.z) >> 22], 1u);
        atomicAdd(&h1[sortable_u32(v.w) >> 22], 1u);
    }
    __syncthreads();
    // suffix scan
    csum[tid] = h1[tid];
    __syncthreads();
    for (int off = 1; off < 1024; off <<= 1) {
        unsigned v = (tid + off < 1024) ? csum[tid + off] : 0u;
        __syncthreads();
        csum[tid] += v;
        __syncthreads();
    }
    unsigned above = (tid < 1023) ? csum[tid + 1] : 0u;
    if (csum[tid] >= (unsigned)k && above < (unsigned)k) { s_cb = tid; s_kAbove = (int)above; }
    __syncthreads();
    int cb = s_cb;
    unsigned kAbove = (unsigned)s_kAbove;

    // pass 2: refine 6 more bits within coarse bin
    for (int i = tid; i < NN / 4; i += 1024) {
        float4 v = s4[i];
        unsigned u;
        u = sortable_u32(v.x); if ((int)(u >> 22) == cb) atomicAdd(&h2[(u >> 16) & 63], 1u);
        u = sortable_u32(v.y); if ((int)(u >> 22) == cb) atomicAdd(&h2[(u >> 16) & 63], 1u);
        u = sortable_u32(v.z); if ((int)(u >> 22) == cb) atomicAdd(&h2[(u >> 16) & 63], 1u);
        u = sortable_u32(v.w); if ((int)(u >> 22) == cb) atomicAdd(&h2[(u >> 16) & 63], 1u);
    }
    __syncthreads();
    if (tid == 0) {
        unsigned run = kAbove;
        int f = 0;
        for (int b = 63; b >= 0; b--) {
            run += h2[b];
            if (run >= (unsigned)k) { f = b; break; }
        }
        s_T16 = (cb << 6) | f;
    }
    __syncthreads();
    int T16 = s_T16;

    // pass 3: collect candidates
    for (int i = tid; i < NN / 4; i += 1024) {
        float4 v = s4[i];
        float vs[4] = {v.x, v.y, v.z, v.w};
#pragma unroll
        for (int c = 0; c < 4; c++) {
            unsigned u = sortable_u32(vs[c]);
            if ((int)(u >> 16) >= T16) {
                int p = atomicAdd(&s_cnt, 1);
                if (p < 4096) {
                    unsigned idx = (unsigned)(i * 4 + c);
                    sk[p] = ((unsigned long long)u << 32) |
                            (unsigned long long)(0xFFFFFFFFu - idx);
                }
            }
        }
    }
    __syncthreads();
    int cnt = s_cnt; if (cnt > 4096) cnt = 4096;
    int n = k; while (n < cnt) n <<= 1;
    for (int i = tid; i < n; i += 1024) if (i >= cnt) sk[i] = 0ULL;
    __syncthreads();
    // bitonic sort (descending at [0..n))
    for (int size = 2; size <= n; size <<= 1) {
        for (int stride = size >> 1; stride; stride >>= 1) {
            for (int i = tid; i < n; i += 1024) {
                int j = i ^ stride;
                if (j > i) {
                    bool asc = (i & size) != 0;
                    unsigned long long a = sk[i], b = sk[j];
                    if ((a > b) == asc) { sk[i] = b; sk[j] = a; }
                }
            }
            __syncthreads();
        }
    }
    if (tid < k) {
        unsigned long long key = sk[tid];
        int idx = (int)(0xFFFFFFFFu - (unsigned)(key & 0xFFFFFFFFu));
        if (idx < 0) idx = 0; if (idx >= NN) idx = NN - 1;   // safety
        idx_out[tid] = idx;
        tv_out[tid] = tanhf(scores[idx]);
    }
}

// ---------------- matrix GRU: one block per output column ----------------
template <int COLS>
__global__ __launch_bounds__(128) void gru_kernel(
    const float* __restrict__ X,
    const int* __restrict__ idx, const float* __restrict__ tv,
    const float* __restrict__ Wu, const float* __restrict__ Uu, const float* __restrict__ Bu,
    const float* __restrict__ Wr, const float* __restrict__ Ur, const float* __restrict__ Br,
    const float* __restrict__ Wh, const float* __restrict__ Uh, const float* __restrict__ Bh,
    const float* __restrict__ Qin, float* __restrict__ Qout) {
    __shared__ __align__(16) float zs[128];
    __shared__ __align__(16) float qs[128];
    __shared__ __align__(16) float rq[128];
    int c = blockIdx.x, r = threadIdx.x;
    zs[r] = X[(size_t)idx[c] * 128 + r] * tv[c];
    float q = Qin[r * COLS + c];
    qs[r] = q;
    __syncthreads();

    const float4* zr  = reinterpret_cast<const float4*>(zs);
    const float4* qr  = reinterpret_cast<const float4*>(qs);
    const float4* pwu = reinterpret_cast<const float4*>(Wu + r * 128);
    const float4* puu = reinterpret_cast<const float4*>(Uu + r * 128);
    const float4* pwr = reinterpret_cast<const float4*>(Wr + r * 128);
    const float4* pur = reinterpret_cast<const float4*>(Ur + r * 128);
    const float4* pwh = reinterpret_cast<const float4*>(Wh + r * 128);
    float au = 0.f, ar = 0.f, hw = 0.f;
#pragma unroll 8
    for (int i = 0; i < 32; i++) {
        float4 z4 = zr[i], q4 = qr[i];
        float4 a = pwu[i]; au += a.x * z4.x + a.y * z4.y + a.z * z4.z + a.w * z4.w;
        float4 b = puu[i]; au += b.x * q4.x + b.y * q4.y + b.z * q4.z + b.w * q4.w;
        float4 cc = pwr[i]; ar += cc.x * z4.x + cc.y * z4.y + cc.z * z4.z + cc.w * z4.w;
        float4 d = pur[i]; ar += d.x * q4.x + d.y * q4.y + d.z * q4.z + d.w * q4.w;
        float4 e = pwh[i]; hw += e.x * z4.x + e.y * z4.y + e.z * z4.z + e.w * z4.w;
    }
    float upd = 1.f / (1.f + expf(-(au + Bu[r * COLS + c])));
    float rst = 1.f / (1.f + expf(-(ar + Br[r * COLS + c])));
    rq[r] = rst * q;
    __syncthreads();
    const float4* puh = reinterpret_cast<const float4*>(Uh + r * 128);
    const float4* rq4 = reinterpret_cast<const float4*>(rq);
    float hu = 0.f;
#pragma unroll 8
    for (int i = 0; i < 32; i++) {
        float4 a = puh[i]; float4 v = rq4[i];
        hu += a.x * v.x + a.y * v.y + a.z * v.z + a.w * v.w;
    }
    float hcap = tanhf(hw + hu + Bh[r * COLS + c]);
    Qout[r * COLS + c] = (1.f - upd) * q + upd * hcap;
}

// ---------------- GEMM: XW[N,BN] = X[N,128] @ Q[128,BN]  (packed f32x2 FMA) ----------------
template <int BN, int TN>
__global__ __launch_bounds__(256) void gemm_kernel(
    const float* __restrict__ X, const float* __restrict__ Q,
    float* __restrict__ XW, int n) {
    constexpr int PITCH = 132;
    extern __shared__ float smem[];
    float* Xs = smem;                     // [128][PITCH] transposed: Xs[k][m]
    float* Qs = smem + 128 * PITCH;       // [128][BN]
    const int tid = threadIdx.x;
    const int tx = tid & 15, ty = tid >> 4;
    const int m0 = blockIdx.x * 128;

#pragma unroll
    for (int it = 0; it < 16; ++it) {
        int f = it * 256 + tid;           // float4 index over 128x128 tile
        int m = f >> 5, k4 = f & 31;
        float4 v = make_float4(0.f, 0.f, 0.f, 0.f);
        int gm = m0 + m;
        if (gm < n) v = reinterpret_cast<const float4*>(X)[(size_t)gm * 32 + k4];
        int k = k4 * 4;
        Xs[(k + 0) * PITCH + m] = v.x;
        Xs[(k + 1) * PITCH + m] = v.y;
        Xs[(k + 2) * PITCH + m] = v.z;
        Xs[(k + 3) * PITCH + m] = v.w;
    }
    constexpr int QF4 = 128 * BN / 4;
    for (int f = tid; f < QF4; f += 256)
        reinterpret_cast<float4*>(Qs)[f] = reinterpret_cast<const float4*>(Q)[f];
    __syncthreads();

    constexpr int TP = TN / 2;            // packed pairs along N
    unsigned long long acc2[8][TP];
#pragma unroll
    for (int i = 0; i < 8; i++)
#pragma unroll
        for (int j = 0; j < TP; j++) acc2[i][j] = 0ULL;

    const int mb = ty * 8, nb = tx * TN;
    const unsigned long long* Qs2 = reinterpret_cast<const unsigned long long*>(Qs);
#pragma unroll 4
    for (int k = 0; k < 128; k++) {
        float a[8];
        float4 a0 = *reinterpret_cast<const float4*>(&Xs[k * PITCH + mb]);
        float4 a1 = *reinterpret_cast<const float4*>(&Xs[k * PITCH + mb + 4]);
        a[0] = a0.x; a[1] = a0.y; a[2] = a0.z; a[3] = a0.w;
        a[4] = a1.x; a[5] = a1.y; a[6] = a1.z; a[7] = a1.w;
        unsigned long long b2[TP];
        const unsigned long long* bq = Qs2 + (k * BN + nb) / 2;
#pragma unroll
        for (int j = 0; j < TP; j++) b2[j] = bq[j];
#pragma unroll
        for (int i = 0; i < 8; i++) {
            unsigned long long aa = bcast2(a[i]);
#pragma unroll
            for (int j = 0; j < TP; j++)
                fma2(acc2[i][j], aa, b2[j]);
        }
    }

#pragma unroll
    for (int i = 0; i < 8; i++) {
        int gm = m0 + mb + i;
        if (gm < n) {
#pragma unroll
            for (int j4 = 0; j4 < TP / 2; j4++) {
                float2 lo = unpack2(acc2[i][j4 * 2 + 0]);
                float2 hi = unpack2(acc2[i][j4 * 2 + 1]);
                float4 o; o.x = lo.x; o.y = lo.y; o.z = hi.x; o.w = hi.y;
                reinterpret_cast<float4*>(XW + (size_t)gm * BN + nb)[j4] = o;
            }
        }
    }
}

// ---------------- CSR build ----------------
__global__ void deg_kernel(const int* __restrict__ dst, int* __restrict__ deg) {
    int i = blockIdx.x * blockDim.x + threadIdx.x;
    if (i < EE) atomicAdd(&deg[dst[i]], 1);
}

// Single block: exclusive scan of deg[NN] -> rowptr; deg becomes cursor copy.
__global__ __launch_bounds__(1024) void scan_kernel(int* __restrict__ deg,
                                                    int* __restrict__ rowptr) {
    __shared__ int sums[1024];
    int tid = threadIdx.x;
    const int CH = (NN + 1023) / 1024;   // 49
    int s0 = tid * CH;
    int s = 0;
    for (int j = 0; j < CH; j++) {
        int i = s0 + j;
        if (i < NN) s += deg[i];
    }
    sums[tid] = s;
    __syncthreads();
    for (int off = 1; off < 1024; off <<= 1) {
        int v = (tid >= off) ? sums[tid - off] : 0;
        __syncthreads();
        sums[tid] += v;
        __syncthreads();
    }
    int run = (tid == 0) ? 0 : sums[tid - 1];
    for (int j = 0; j < CH; j++) {
        int i = s0 + j;
        if (i < NN) {
            int d = deg[i];
            rowptr[i] = run;
            deg[i] = run;    // cursor
            run += d;
        }
    }
    if (tid == 1023) rowptr[NN] = sums[1023];
}

__global__ void fill_kernel(const int* __restrict__ dst, int* __restrict__ cursor,
                            int* __restrict__ eid) {
    int e = blockIdx.x * blockDim.x + threadIdx.x;
    if (e < EE) {
        int p = atomicAdd(&cursor[dst[e]], 1);
        eid[p] = e;
    }
}

// ---------------- gather: out[d] = relu(sum_{e: dst==d} w_e * XW[src_e]) ----------------
template <int COLS>
__global__ __launch_bounds__(256) void gather_kernel(
    const float* __restrict__ XW, const int* __restrict__ src,
    const float* __restrict__ ew, const int* __restrict__ rowptr,
    const int* __restrict__ eid, float* __restrict__ out) {
    constexpr int L = COLS / 4;          // lanes per node
    constexpr int NPW = 32 / L;          // nodes per warp
    int warp = (blockIdx.x * blockDim.x + threadIdx.x) >> 5;
    int lane = threadIdx.x & 31;
    int node = warp * NPW + lane / L;
    int cl = lane % L;
    if (node >= NN) return;
    int b = rowptr[node], e2 = rowptr[node + 1];
    float4 acc = make_float4(0.f, 0.f, 0.f, 0.f);
    const float4* XW4 = reinterpret_cast<const float4*>(XW);
    for (int j = b; j < e2; j++) {
        int e = eid[j];
        int s = src[e];
        float w = ew[e];
        float4 v = XW4[(size_t)s * L + cl];
        acc.x = fmaf(w, v.x, acc.x);
        acc.y = fmaf(w, v.y, acc.y);
        acc.z = fmaf(w, v.z, acc.z);
        acc.w = fmaf(w, v.w, acc.w);
    }
    acc.x = fmaxf(acc.x, 0.f); acc.y = fmaxf(acc.y, 0.f);
    acc.z = fmaxf(acc.z, 0.f); acc.w = fmaxf(acc.w, 0.f);
    reinterpret_cast<float4*>(out)[(size_t)node * L + cl] = acc;
}

// ---------------- host orchestration ----------------
struct Scratch {
    float* scores; int* idx; float* tv; float* inv;
    float* qa0; float* qb0; float* qa1; float* qb1; float* xw; float* h1;
    int* rowptr; int* cursor; int* eid;
};

static void run_step(const float* X, const float* mask_t, const float* const* W,
                     const float* Qin, float* Qout,
                     const int* src, const float* ew,
                     float* outbuf, int cols, int layer, const Scratch& S) {
    const int k = cols;
    scores_kernel<<<(NN + 7) / 8, 256>>>(X, W[9], mask_t, S.inv + layer, S.scores);
    topk_kernel<<<1, 1024>>>(S.scores, k, S.idx, S.tv);
    if (cols == 128)
        gru_kernel<128><<<128, 128>>>(X, S.idx, S.tv, W[0], W[1], W[2], W[3], W[4],
                                      W[5], W[6], W[7], W[8], Qin, Qout);
    else
        gru_kernel<64><<<64, 128>>>(X, S.idx, S.tv, W[0], W[1], W[2], W[3], W[4],
                                    W[5], W[6], W[7], W[8], Qin, Qout);
    int gblocks = (NN + 127) / 128;
    if (cols == 128) {
        size_t sm = (size_t)(128 * 132 + 128 * 128) * sizeof(float);
        cudaFuncSetAttribute(gemm_kernel<128, 8>, cudaFuncAttributeMaxDynamicSharedMemorySize, (int)sm);
        gemm_kernel<128, 8><<<gblocks, 256, sm>>>(X, Qout, S.xw, NN);
    } else {
        size_t sm = (size_t)(128 * 132 + 128 * 64) * sizeof(float);
        cudaFuncSetAttribute(gemm_kernel<64, 4>, cudaFuncAttributeMaxDynamicSharedMemorySize, (int)sm);
        gemm_kernel<64, 4><<<gblocks, 256, sm>>>(X, Qout, S.xw, NN);
    }
    // gather (replaces zero + atomic scatter + relu)
    if (cols == 128) {
        int warps = NN;                  // 1 node / warp
        gather_kernel<128><<<(warps * 32 + 255) / 256, 256>>>(S.xw, src, ew,
                                                              S.rowptr, S.eid, outbuf);
    } else {
        int warps = (NN + 1) / 2;        // 2 nodes / warp
        gather_kernel<64><<<(warps * 32 + 255) / 256, 256>>>(S.xw, src, ew,
                                                             S.rowptr, S.eid, outbuf);
    }
}

extern "C" void kernel_launch(void* const* d_in, const int* in_sizes, int n_in,
                              void* d_out, int out_size) {
    const float* node_embs = (const float*)d_in[0];
    const float* mask      = (const float*)d_in[1];
    const int*   esrc      = (const int*)d_in[2];
    const int*   edst      = (const int*)d_in[3];
    const float* ew        = (const float*)d_in[4];
    const float* gcn_w0    = (const float*)d_in[5];
    const float* gcn_w1    = (const float*)d_in[6];
    const float* L0[10]; for (int i = 0; i < 10; i++) L0[i] = (const float*)d_in[7 + i];
    const float* L1[10]; for (int i = 0; i < 10; i++) L1[i] = (const float*)d_in[17 + i];
    float* out = (float*)d_out;

    Scratch S;
    cudaGetSymbolAddress((void**)&S.scores, g_scores);
    cudaGetSymbolAddress((void**)&S.idx,    g_idx);
    cudaGetSymbolAddress((void**)&S.tv,     g_tv);
    cudaGetSymbolAddress((void**)&S.inv,    g_inv);
    cudaGetSymbolAddress((void**)&S.qa0,    g_QA0);
    cudaGetSymbolAddress((void**)&S.qb0,    g_QB0);
    cudaGetSymbolAddress((void**)&S.qa1,    g_QA1);
    cudaGetSymbolAddress((void**)&S.qb1,    g_QB1);
    cudaGetSymbolAddress((void**)&S.xw,     g_XW);
    cudaGetSymbolAddress((void**)&S.h1,     g_h1);
    cudaGetSymbolAddress((void**)&S.rowptr, g_rowptr);
    cudaGetSymbolAddress((void**)&S.cursor, g_cursor);
    cudaGetSymbolAddress((void**)&S.eid,    g_eid);

    // init GRU states from gcn weights (device-to-device, capturable)
    cudaMemcpyAsync(S.qa0, gcn_w0, 128 * 128 * sizeof(float), cudaMemcpyDeviceToDevice, 0);
    cudaMemcpyAsync(S.qa1, gcn_w1, 128 * 64 * sizeof(float),  cudaMemcpyDeviceToDevice, 0);
    norm_kernel<<<2, 128>>>(L0[9], L1[9], S.inv);

    for (int t = 0; t < TT; t++) {
        const float* Xt = node_embs + (size_t)t * NN * F0;
        const float* mt = mask + (size_t)t * NN;
        const int*   st = esrc + (size_t)t * EE;
        const int*   dt = edst + (size_t)t * EE;
        const float* wt = ew   + (size_t)t * EE;
        const float* q0in  = (t & 1) ? S.qb0 : S.qa0;
        float*       q0out = (t & 1) ? S.qa0 : S.qb0;
        const float* q1in  = (t & 1) ? S.qb1 : S.qa1;
        float*       q1out = (t & 1) ? S.qa1 : S.qb1;

        // build CSR for this timestep (shared by both layers)
        cudaMemsetAsync(S.cursor, 0, NN * sizeof(int), 0);
        deg_kernel<<<(EE + 255) / 256, 256>>>(dt, S.cursor);
        scan_kernel<<<1, 1024>>>(S.cursor, S.rowptr);
        fill_kernel<<<(EE + 255) / 256, 256>>>(dt, S.cursor, S.eid);

        // layer 0: X = node_embs[t] -> h1
        run_step(Xt, mt, L0, q0in, q0out, st, wt, S.h1, 128, 0, S);
        // layer 1: X = h1 -> out[t]
        run_step(S.h1, mt, L1, q1in, q1out, st, wt,
                 out + (size_t)t * NN * F2, 64, 1, S);
    }
}

// round 10
// speedup vs baseline: 2.4712x; 2.4712x over previous
#include <cuda_runtime.h>
#include <math.h>

#define NN 50000
#define EE 400000
#define TT 4
#define F0 128
#define F2 64

// ---------------- device scratch (no allocs allowed) ----------------
__device__ float g_scores0[TT * NN];
__device__ float g_scores1[TT * NN];
__device__ int   g_idx[128];
__device__ float g_tv[128];
__device__ float g_inv[2];
__device__ float g_Q0s[TT][128 * 128];
__device__ float g_Q1s[TT][128 * 64];
__device__ float g_XW[(size_t)NN * 128];
__device__ float g_h1[TT][NN * 128];
__device__ int   g_rowptr[TT][NN + 1];
__device__ int   g_cursor[TT][NN];
__device__ int   g_eid[TT][EE];

// ---------------- helpers ----------------
__device__ __forceinline__ unsigned sortable_u32(float f) {
    unsigned u = __float_as_uint(f);
    return (u & 0x80000000u) ? ~u : (u | 0x80000000u);
}

// ---------------- scorer norms ----------------
__global__ void norm_kernel(const float* __restrict__ s0, const float* __restrict__ s1,
                            float* __restrict__ inv) {
    const float* s = blockIdx.x ? s1 : s0;
    int t = threadIdx.x;           // 128 threads
    float v = s[t]; v *= v;
    __shared__ float red[4];
    for (int o = 16; o; o >>= 1) v += __shfl_xor_sync(0xFFFFFFFFu, v, o);
    if ((t & 31) == 0) red[t >> 5] = v;
    __syncthreads();
    if (t == 0) inv[blockIdx.x] = rsqrtf(red[0] + red[1] + red[2] + red[3]);
}

// ---------------- scores (generic): one warp per node ----------------
__global__ __launch_bounds__(256) void scores_kernel(
    const float* __restrict__ X, const float* __restrict__ scorer,
    const float* __restrict__ mask_t, const float* __restrict__ invp,
    float* __restrict__ out) {
    int warp = (blockIdx.x * blockDim.x + threadIdx.x) >> 5;
    int lane = threadIdx.x & 31;
    if (warp >= NN) return;
    float4 x = reinterpret_cast<const float4*>(X)[(size_t)warp * 32 + lane];
    float4 s = reinterpret_cast<const float4*>(scorer)[lane];
    float d = x.x * s.x + x.y * s.y + x.z * s.z + x.w * s.w;
    for (int o = 16; o; o >>= 1) d += __shfl_xor_sync(0xFFFFFFFFu, d, o);
    if (lane == 0) out[warp] = d * (*invp) + mask_t[warp];
}

// ---------------- scores for ALL layer-0 timesteps in one launch ----------------
__global__ __launch_bounds__(256) void scores0_all_kernel(
    const float* __restrict__ X, const float* __restrict__ scorer,
    const float* __restrict__ mask, const float* __restrict__ invp,
    float* __restrict__ out) {
    int warp = (blockIdx.x * blockDim.x + threadIdx.x) >> 5;  // flat (t,node)
    int lane = threadIdx.x & 31;
    if (warp >= TT * NN) return;
    float4 x = reinterpret_cast<const float4*>(X)[(size_t)warp * 32 + lane];
    float4 s = reinterpret_cast<const float4*>(scorer)[lane];
    float d = x.x * s.x + x.y * s.y + x.z * s.z + x.w * s.w;
    for (int o = 16; o; o >>= 1) d += __shfl_xor_sync(0xFFFFFFFFu, d, o);
    if (lane == 0) out[warp] = d * invp[0] + mask[warp];
}

// ---------------- fused single-block topk ----------------
__global__ __launch_bounds__(1024) void topk_kernel(
    const float* __restrict__ scores, int k,
    int* __restrict__ idx_out, float* __restrict__ tv_out) {
    __shared__ unsigned h1[1024];
    __shared__ unsigned csum[1024];
    __shared__ unsigned h2[64];
    __shared__ unsigned long long sk[4096];
    __shared__ int s_cb, s_kAbove, s_T16, s_cnt;
    int tid = threadIdx.x;
    h1[tid] = 0;
    if (tid < 64) h2[tid] = 0;
    if (tid == 0) s_cnt = 0;
    __syncthreads();

    const float4* s4 = reinterpret_cast<const float4*>(scores);
    for (int i = tid; i < NN / 4; i += 1024) {
        float4 v = s4[i];
        atomicAdd(&h1[sortable_u32(v.x) >> 22], 1u);
        atomicAdd(&h1[sortable_u32(v.y) >> 22], 1u);
        atomicAdd(&h1[sortable_u32(v.z) >> 22], 1u);
        atomicAdd(&h1[sortable_u32(v.w) >> 22], 1u);
    }
    __syncthreads();
    csum[tid] = h1[tid];
    __syncthreads();
    for (int off = 1; off < 1024; off <<= 1) {
        unsigned v = (tid + off < 1024) ? csum[tid + off] : 0u;
        __syncthreads();
        csum[tid] += v;
        __syncthreads();
    }
    unsigned above = (tid < 1023) ? csum[tid + 1] : 0u;
    if (csum[tid] >= (unsigned)k && above < (unsigned)k) { s_cb = tid; s_kAbove = (int)above; }
    __syncthreads();
    int cb = s_cb;
    unsigned kAbove = (unsigned)s_kAbove;

    for (int i = tid; i < NN / 4; i += 1024) {
        float4 v = s4[i];
        unsigned u;
        u = sortable_u32(v.x); if ((int)(u >> 22) == cb) atomicAdd(&h2[(u >> 16) & 63], 1u);
        u = sortable_u32(v.y); if ((int)(u >> 22) == cb) atomicAdd(&h2[(u >> 16) & 63], 1u);
        u = sortable_u32(v.z); if ((int)(u >> 22) == cb) atomicAdd(&h2[(u >> 16) & 63], 1u);
        u = sortable_u32(v.w); if ((int)(u >> 22) == cb) atomicAdd(&h2[(u >> 16) & 63], 1u);
    }
    __syncthreads();
    if (tid == 0) {
        unsigned run = kAbove;
        int f = 0;
        for (int b = 63; b >= 0; b--) {
            run += h2[b];
            if (run >= (unsigned)k) { f = b; break; }
        }
        s_T16 = (cb << 6) | f;
    }
    __syncthreads();
    int T16 = s_T16;

    for (int i = tid; i < NN / 4; i += 1024) {
        float4 v = s4[i];
        float vs[4] = {v.x, v.y, v.z, v.w};
#pragma unroll
        for (int c = 0; c < 4; c++) {
            unsigned u = sortable_u32(vs[c]);
            if ((int)(u >> 16) >= T16) {
                int p = atomicAdd(&s_cnt, 1);
                if (p < 4096) {
                    unsigned idx = (unsigned)(i * 4 + c);
                    sk[p] = ((unsigned long long)u << 32) |
                            (unsigned long long)(0xFFFFFFFFu - idx);
                }
            }
        }
    }
    __syncthreads();
    int cnt = s_cnt; if (cnt > 4096) cnt = 4096;
    int n = k; while (n < cnt) n <<= 1;
    for (int i = tid; i < n; i += 1024) if (i >= cnt) sk[i] = 0ULL;
    __syncthreads();
    for (int size = 2; size <= n; size <<= 1) {
        for (int stride = size >> 1; stride; stride >>= 1) {
            for (int i = tid; i < n; i += 1024) {
                int j = i ^ stride;
                if (j > i) {
                    bool asc = (i & size) != 0;
                    unsigned long long a = sk[i], b = sk[j];
                    if ((a > b) == asc) { sk[i] = b; sk[j] = a; }
                }
            }
            __syncthreads();
        }
    }
    if (tid < k) {
        unsigned long long key = sk[tid];
        int idx = (int)(0xFFFFFFFFu - (unsigned)(key & 0xFFFFFFFFu));
        if (idx < 0) idx = 0; if (idx >= NN) idx = NN - 1;   // safety
        idx_out[tid] = idx;
        tv_out[tid] = tanhf(scores[idx]);
    }
}

// ---------------- matrix GRU: one block per output column ----------------
template <int COLS>
__global__ __launch_bounds__(128) void gru_kernel(
    const float* __restrict__ X,
    const int* __restrict__ idx, const float* __restrict__ tv,
    const float* __restrict__ Wu, const float* __restrict__ Uu, const float* __restrict__ Bu,
    const float* __restrict__ Wr, const float* __restrict__ Ur, const float* __restrict__ Br,
    const float* __restrict__ Wh, const float* __restrict__ Uh, const float* __restrict__ Bh,
    const float* __restrict__ Qin, float* __restrict__ Qout) {
    __shared__ __align__(16) float zs[128];
    __shared__ __align__(16) float qs[128];
    __shared__ __align__(16) float rq[128];
    int c = blockIdx.x, r = threadIdx.x;
    zs[r] = X[(size_t)idx[c] * 128 + r] * tv[c];
    float q = Qin[r * COLS + c];
    qs[r] = q;
    __syncthreads();

    const float4* zr  = reinterpret_cast<const float4*>(zs);
    const float4* qr  = reinterpret_cast<const float4*>(qs);
    const float4* pwu = reinterpret_cast<const float4*>(Wu + r * 128);
    const float4* puu = reinterpret_cast<const float4*>(Uu + r * 128);
    const float4* pwr = reinterpret_cast<const float4*>(Wr + r * 128);
    const float4* pur = reinterpret_cast<const float4*>(Ur + r * 128);
    const float4* pwh = reinterpret_cast<const float4*>(Wh + r * 128);
    float au = 0.f, ar = 0.f, hw = 0.f;
#pragma unroll 8
    for (int i = 0; i < 32; i++) {
        float4 z4 = zr[i], q4 = qr[i];
        float4 a = pwu[i]; au += a.x * z4.x + a.y * z4.y + a.z * z4.z + a.w * z4.w;
        float4 b = puu[i]; au += b.x * q4.x + b.y * q4.y + b.z * q4.z + b.w * q4.w;
        float4 cc = pwr[i]; ar += cc.x * z4.x + cc.y * z4.y + cc.z * z4.z + cc.w * z4.w;
        float4 d = pur[i]; ar += d.x * q4.x + d.y * q4.y + d.z * q4.z + d.w * q4.w;
        float4 e = pwh[i]; hw += e.x * z4.x + e.y * z4.y + e.z * z4.z + e.w * z4.w;
    }
    float upd = 1.f / (1.f + expf(-(au + Bu[r * COLS + c])));
    float rst = 1.f / (1.f + expf(-(ar + Br[r * COLS + c])));
    rq[r] = rst * q;
    __syncthreads();
    const float4* puh = reinterpret_cast<const float4*>(Uh + r * 128);
    const float4* rq4 = reinterpret_cast<const float4*>(rq);
    float hu = 0.f;
#pragma unroll 8
    for (int i = 0; i < 32; i++) {
        float4 a = puh[i]; float4 v = rq4[i];
        hu += a.x * v.x + a.y * v.y + a.z * v.z + a.w * v.w;
    }
    float hcap = tanhf(hw + hu + Bh[r * COLS + c]);
    Qout[r * COLS + c] = (1.f - upd) * q + upd * hcap;
}

// ---------------- GEMM: XW[N,BN] = X[N,128] @ Q[128,BN], K chunked 2x64 ----------------
template <int BN, int TN>
__global__ __launch_bounds__(256) void gemm_kernel(
    const float* __restrict__ X, const float* __restrict__ Q,
    float* __restrict__ XW, int n) {
    constexpr int PITCH = 132;
    extern __shared__ float smem[];
    float* Xs = smem;                     // [64][PITCH] transposed: Xs[k][m]
    float* Qs = smem + 64 * PITCH;        // [128][BN]
    const int tid = threadIdx.x;
    const int tx = tid & 15, ty = tid >> 4;
    const int m0 = blockIdx.x * 128;

    constexpr int QF4 = 128 * BN / 4;
    for (int f = tid; f < QF4; f += 256)
        reinterpret_cast<float4*>(Qs)[f] = reinterpret_cast<const float4*>(Q)[f];

    float acc[8][TN];
#pragma unroll
    for (int i = 0; i < 8; i++)
#pragma unroll
        for (int j = 0; j < TN; j++) acc[i][j] = 0.f;

    const int mb = ty * 8, nb = tx * TN;

#pragma unroll
    for (int kc = 0; kc < 2; kc++) {
        if (kc) __syncthreads();          // WAR: prev chunk's reads done
        // load Xs chunk: 128 rows x 16 float4
#pragma unroll
        for (int it = 0; it < 8; ++it) {
            int f = it * 256 + tid;
            int m = f >> 4, k4 = f & 15;
            float4 v = make_float4(0.f, 0.f, 0.f, 0.f);
            int gm = m0 + m;
            if (gm < n) v = reinterpret_cast<const float4*>(X)[(size_t)gm * 32 + kc * 16 + k4];
            int k = k4 * 4;
            Xs[(k + 0) * PITCH + m] = v.x;
            Xs[(k + 1) * PITCH + m] = v.y;
            Xs[(k + 2) * PITCH + m] = v.z;
            Xs[(k + 3) * PITCH + m] = v.w;
        }
        __syncthreads();
#pragma unroll 4
        for (int k = 0; k < 64; k++) {
            float a[8], b[TN];
            float4 a0 = *reinterpret_cast<const float4*>(&Xs[k * PITCH + mb]);
            float4 a1 = *reinterpret_cast<const float4*>(&Xs[k * PITCH + mb + 4]);
            a[0] = a0.x; a[1] = a0.y; a[2] = a0.z; a[3] = a0.w;
            a[4] = a1.x; a[5] = a1.y; a[6] = a1.z; a[7] = a1.w;
#pragma unroll
            for (int j4 = 0; j4 < TN / 4; j4++) {
                float4 bq = *reinterpret_cast<const float4*>(&Qs[(kc * 64 + k) * BN + nb + j4 * 4]);
                b[j4 * 4 + 0] = bq.x; b[j4 * 4 + 1] = bq.y;
                b[j4 * 4 + 2] = bq.z; b[j4 * 4 + 3] = bq.w;
            }
#pragma unroll
            for (int i = 0; i < 8; i++)
#pragma unroll
                for (int j = 0; j < TN; j++)
                    acc[i][j] = fmaf(a[i], b[j], acc[i][j]);
        }
    }

#pragma unroll
    for (int i = 0; i < 8; i++) {
        int gm = m0 + mb + i;
        if (gm < n) {
#pragma unroll
            for (int j4 = 0; j4 < TN / 4; j4++) {
                float4 o;
                o.x = acc[i][j4 * 4 + 0]; o.y = acc[i][j4 * 4 + 1];
                o.z = acc[i][j4 * 4 + 2]; o.w = acc[i][j4 * 4 + 3];
                reinterpret_cast<float4*>(XW + (size_t)gm * BN + nb)[j4] = o;
            }
        }
    }
}

// ---------------- batched CSR build (all timesteps) ----------------
__global__ void deg_all_kernel(const int* __restrict__ dst, int* __restrict__ deg) {
    int i = blockIdx.x * blockDim.x + threadIdx.x;   // flat (t,e)
    if (i < TT * EE) {
        int t = i / EE;
        atomicAdd(&deg[t * NN + dst[i]], 1);
    }
}

// One block per timestep: exclusive scan of deg -> rowptr; deg becomes cursor.
__global__ __launch_bounds__(1024) void scan_all_kernel(int* __restrict__ deg_all,
                                                        int* __restrict__ rowptr_all) {
    __shared__ int sums[1024];
    int* deg = deg_all + blockIdx.x * NN;
    int* rowptr = rowptr_all + blockIdx.x * (NN + 1);
    int tid = threadIdx.x;
    const int CH = (NN + 1023) / 1024;   // 49
    int s0 = tid * CH;
    int s = 0;
    for (int j = 0; j < CH; j++) {
        int i = s0 + j;
        if (i < NN) s += deg[i];
    }
    sums[tid] = s;
    __syncthreads();
    for (int off = 1; off < 1024; off <<= 1) {
        int v = (tid >= off) ? sums[tid - off] : 0;
        __syncthreads();
        sums[tid] += v;
        __syncthreads();
    }
    int run = (tid == 0) ? 0 : sums[tid - 1];
    for (int j = 0; j < CH; j++) {
        int i = s0 + j;
        if (i < NN) {
            int d = deg[i];
            rowptr[i] = run;
            deg[i] = run;    // cursor
            run += d;
        }
    }
    if (tid == 1023) rowptr[NN] = sums[1023];
}

__global__ void fill_all_kernel(const int* __restrict__ dst, int* __restrict__ cursor,
                                int* __restrict__ eid) {
    int i = blockIdx.x * blockDim.x + threadIdx.x;   // flat (t,e)
    if (i < TT * EE) {
        int t = i / EE, e = i - t * EE;
        int p = atomicAdd(&cursor[t * NN + dst[i]], 1);
        eid[t * EE + p] = e;
    }
}

// ---------------- gather: out[d] = relu(sum_{e: dst==d} w_e * XW[src_e]) ----------------
template <int COLS>
__global__ __launch_bounds__(256) void gather_kernel(
    const float* __restrict__ XW, const int* __restrict__ src,
    const float* __restrict__ ew, const int* __restrict__ rowptr,
    const int* __restrict__ eid, float* __restrict__ out) {
    constexpr int L = COLS / 4;          // lanes per node
    constexpr int NPW = 32 / L;          // nodes per warp
    int warp = (blockIdx.x * blockDim.x + threadIdx.x) >> 5;
    int lane = threadIdx.x & 31;
    int node = warp * NPW + lane / L;
    int cl = lane % L;
    if (node >= NN) return;
    int b = rowptr[node], e2 = rowptr[node + 1];
    float4 acc = make_float4(0.f, 0.f, 0.f, 0.f);
    const float4* XW4 = reinterpret_cast<const float4*>(XW);
    for (int j = b; j < e2; j++) {
        int e = eid[j];
        int s = src[e];
        float w = ew[e];
        float4 v = XW4[(size_t)s * L + cl];
        acc.x = fmaf(w, v.x, acc.x);
        acc.y = fmaf(w, v.y, acc.y);
        acc.z = fmaf(w, v.z, acc.z);
        acc.w = fmaf(w, v.w, acc.w);
    }
    acc.x = fmaxf(acc.x, 0.f); acc.y = fmaxf(acc.y, 0.f);
    acc.z = fmaxf(acc.z, 0.f); acc.w = fmaxf(acc.w, 0.f);
    reinterpret_cast<float4*>(out)[(size_t)node * L + cl] = acc;
}

// ---------------- host orchestration ----------------
extern "C" void kernel_launch(void* const* d_in, const int* in_sizes, int n_in,
                              void* d_out, int out_size) {
    const float* node_embs = (const float*)d_in[0];
    const float* mask      = (const float*)d_in[1];
    const int*   esrc      = (const int*)d_in[2];
    const int*   edst      = (const int*)d_in[3];
    const float* ew        = (const float*)d_in[4];
    const float* gcn_w0    = (const float*)d_in[5];
    const float* gcn_w1    = (const float*)d_in[6];
    const float* L0[10]; for (int i = 0; i < 10; i++) L0[i] = (const float*)d_in[7 + i];
    const float* L1[10]; for (int i = 0; i < 10; i++) L1[i] = (const float*)d_in[17 + i];
    float* out = (float*)d_out;

    float *scores0, *scores1, *tv, *inv, *q0s, *q1s, *xw, *h1;
    int *idx, *rowptr, *cursor, *eid;
    cudaGetSymbolAddress((void**)&scores0, g_scores0);
    cudaGetSymbolAddress((void**)&scores1, g_scores1);
    cudaGetSymbolAddress((void**)&idx,     g_idx);
    cudaGetSymbolAddress((void**)&tv,      g_tv);
    cudaGetSymbolAddress((void**)&inv,     g_inv);
    cudaGetSymbolAddress((void**)&q0s,     g_Q0s);
    cudaGetSymbolAddress((void**)&q1s,     g_Q1s);
    cudaGetSymbolAddress((void**)&xw,      g_XW);
    cudaGetSymbolAddress((void**)&h1,      g_h1);
    cudaGetSymbolAddress((void**)&rowptr,  g_rowptr);
    cudaGetSymbolAddress((void**)&cursor,  g_cursor);
    cudaGetSymbolAddress((void**)&eid,     g_eid);

    // one-time host objects (never destroyed: destroying a stream/event that is
    // part of an active capture would invalidate the harness's capture)
    static cudaStream_t sB = nullptr;
    static cudaEvent_t evStart, evEnd, evGru0[TT], evSc1[TT], evGru1[TT];
    if (!sB) {
        cudaStreamCreateWithFlags(&sB, cudaStreamNonBlocking);
        cudaEventCreateWithFlags(&evStart, cudaEventDisableTiming);
        cudaEventCreateWithFlags(&evEnd,   cudaEventDisableTiming);
        for (int t = 0; t < TT; t++) {
            cudaEventCreateWithFlags(&evGru0[t], cudaEventDisableTiming);
            cudaEventCreateWithFlags(&evSc1[t],  cudaEventDisableTiming);
            cudaEventCreateWithFlags(&evGru1[t], cudaEventDisableTiming);
        }
    }

    size_t sm128 = (size_t)(64 * 132 + 128 * 128) * sizeof(float);  // 99328
    size_t sm64  = (size_t)(64 * 132 + 128 * 64)  * sizeof(float);  // 66560
    cudaFuncSetAttribute(gemm_kernel<128, 8>, cudaFuncAttributeMaxDynamicSharedMemorySize, (int)sm128);
    cudaFuncSetAttribute(gemm_kernel<64, 4>,  cudaFuncAttributeMaxDynamicSharedMemorySize, (int)sm64);

    // fork sB from origin stream
    cudaEventRecord(evStart, 0);
    cudaStreamWaitEvent(sB, evStart, 0);

    // sB: batched CSR for all timesteps
    cudaMemsetAsync(cursor, 0, (size_t)TT * NN * sizeof(int), sB);
    deg_all_kernel<<<(TT * EE + 255) / 256, 256, 0, sB>>>(edst, cursor);
    scan_all_kernel<<<TT, 1024, 0, sB>>>(cursor, rowptr);
    fill_all_kernel<<<(TT * EE + 255) / 256, 256, 0, sB>>>(edst, cursor, eid);

    // origin: norms + all layer-0 scores
    norm_kernel<<<2, 128>>>(L0[9], L1[9], inv);
    scores0_all_kernel<<<(TT * NN + 7) / 8, 256>>>(node_embs, L0[9], mask, inv, scores0);

    const int gblocks = (NN + 127) / 128;
    const int gth128  = ((NN * 32 + 255) / 256);          // 1 node/warp
    const int gth64   = ((((NN + 1) / 2) * 32 + 255) / 256); // 2 nodes/warp

    // layer 0: small chain on origin, big kernels on sB
    for (int t = 0; t < TT; t++) {
        const float* Xt  = node_embs + (size_t)t * NN * F0;
        float*       h1t = h1 + (size_t)t * NN * 128;
        const float* q0in = (t == 0) ? gcn_w0 : (q0s + (size_t)(t - 1) * 128 * 128);
        float*       q0out = q0s + (size_t)t * 128 * 128;

        topk_kernel<<<1, 1024>>>(scores0 + (size_t)t * NN, 128, idx, tv);
        gru_kernel<128><<<128, 128>>>(Xt, idx, tv, L0[0], L0[1], L0[2], L0[3], L0[4],
                                      L0[5], L0[6], L0[7], L0[8], q0in, q0out);
        cudaEventRecord(evGru0[t], 0);
        cudaStreamWaitEvent(sB, evGru0[t], 0);

        gemm_kernel<128, 8><<<gblocks, 256, sm128, sB>>>(Xt, q0out, xw, NN);
        gather_kernel<128><<<gth128, 256, 0, sB>>>(xw, esrc + (size_t)t * EE,
                                                   ew + (size_t)t * EE,
                                                   rowptr + (size_t)t * (NN + 1),
                                                   eid + (size_t)t * EE, h1t);
        scores_kernel<<<(NN + 7) / 8, 256, 0, sB>>>(h1t, L1[9], mask + (size_t)t * NN,
                                                    inv + 1, scores1 + (size_t)t * NN);
        cudaEventRecord(evSc1[t], sB);
    }

    // layer 1
    for (int t = 0; t < TT; t++) {
        float*       h1t = h1 + (size_t)t * NN * 128;
        const float* q1in = (t == 0) ? gcn_w1 : (q1s + (size_t)(t - 1) * 128 * 64);
        float*       q1out = q1s + (size_t)t * 128 * 64;

        cudaStreamWaitEvent(0, evSc1[t], 0);
        topk_kernel<<<1, 1024>>>(scores1 + (size_t)t * NN, 64, idx, tv);
        gru_kernel<64><<<64, 128>>>(h1t, idx, tv, L1[0], L1[1], L1[2], L1[3], L1[4],
                                    L1[5], L1[6], L1[7], L1[8], q1in, q1out);
        cudaEventRecord(evGru1[t], 0);
        cudaStreamWaitEvent(sB, evGru1[t], 0);

        gemm_kernel<64, 4><<<gblocks, 256, sm64, sB>>>(h1t, q1out, xw, NN);
        gather_kernel<64><<<gth64, 256, 0, sB>>>(xw, esrc + (size_t)t * EE,
                                                 ew + (size_t)t * EE,
                                                 rowptr + (size_t)t * (NN + 1),
                                                 eid + (size_t)t * EE,
                                                 out + (size_t)t * NN * F2);
    }

    // join sB back into origin stream
    cudaEventRecord(evEnd, sB);
    cudaStreamWaitEvent(0, evEnd, 0);
}